// round 4
// baseline (speedup 1.0000x reference)
#include <cuda_runtime.h>
#include <cuda_bf16.h>

#define NE      800000
#define NN      50000
#define NTILES  (NE / 128)
#define RSQ2    0.70710678118654752440f

// smem strides (floats)
#define B_WS 68     // scatter W tile row stride
#define B_XS 130    // scatter attr tile row stride
#define D_WS 132    // gather Wcat row stride
#define D_XS 130    // gather x tile row stride

#define B_SMEM (128*B_WS*4 + 128*B_XS*4 + 128*16 + 128*4 + 128*4)              // 104448
#define D_SMEM (192*D_WS*4 + 192*D_XS*4 + 128*16 + 128*4 + 128*4 + 128*4)      // 204800

// scratch (no cudaMalloc allowed)
__device__ float g_h[NN * 64];
__device__ int   g_mask_mode;

// ---------- packed f32x2 helpers ----------
static __device__ __forceinline__ unsigned long long pk2(float x, float y) {
    unsigned long long r;
    asm("mov.b64 %0, {%1, %2};" : "=l"(r) : "f"(x), "f"(y));
    return r;
}
static __device__ __forceinline__ float2 upk2(unsigned long long v) {
    float2 f;
    asm("mov.b64 {%0, %1}, %2;" : "=f"(f.x), "=f"(f.y) : "l"(v));
    return f;
}
static __device__ __forceinline__ void fma2(unsigned long long &d,
                                            unsigned long long a,
                                            unsigned long long b) {
    asm("fma.rn.f32x2 %0, %1, %2, %0;" : "+l"(d) : "l"(a), "l"(b));
}
static __device__ __forceinline__ void red4(float* p, float a, float b, float c, float d) {
    asm volatile("red.global.add.v4.f32 [%0], {%1, %2, %3, %4};"
                 :: "l"(p), "f"(a), "f"(b), "f"(c), "f"(d) : "memory");
}

// ---------- mask dtype ----------
static __device__ __forceinline__ bool get_mask(const void* m, int e, int mode) {
    if (mode == 0) return ((const int*)m)[e] != 0;
    if (mode == 1) return ((const unsigned char*)m)[e] != 0;
    return ((const float*)m)[e] != 0.0f;
}

// classify mask buffer dtype from byte pattern of first 4096 bytes.
// i32 0/1: nonzero bytes only at off%4==0 ; f32 0/1.0: only off%4 in {2,3} ;
// u8 bool: nonzero bytes at all offset classes. Bernoulli(0.5) data => certain.
__global__ void probe_mask_kernel(const unsigned char* __restrict__ m) {
    __shared__ int flag[4];
    int t = threadIdx.x;
    if (t < 4) flag[t] = 0;
    __syncthreads();
    int any = 0;
    for (int i = t; i < 4096; i += 256) any |= (int)m[i];
    if (any) atomicOr(&flag[t & 3], 1);
    __syncthreads();
    if (t == 0) {
        int mode;
        if (flag[1] || (flag[0] && (flag[2] | flag[3]))) mode = 1;   // u8
        else if (flag[2] | flag[3])                      mode = 2;   // f32
        else                                             mode = 0;   // i32
        g_mask_mode = mode;
    }
}

__global__ void zero_h_kernel() {
    float4* p = (float4*)g_h;
    const int n = NN * 64 / 4;
    for (int i = blockIdx.x * blockDim.x + threadIdx.x; i < n; i += gridDim.x * blockDim.x)
        p[i] = make_float4(0.f, 0.f, 0.f, 0.f);
}
__global__ void relu_h_kernel() {
    float4* p = (float4*)g_h;
    const int n = NN * 64 / 4;
    for (int i = blockIdx.x * blockDim.x + threadIdx.x; i < n; i += gridDim.x * blockDim.x) {
        float4 v = p[i];
        v.x = fmaxf(v.x, 0.f); v.y = fmaxf(v.y, 0.f);
        v.z = fmaxf(v.z, 0.f); v.w = fmaxf(v.w, 0.f);
        p[i] = v;
    }
}

// ---------- pass 1: z = (attr @ W_in^T)*dinv ; scatter phase*z into g_h ----------
// 256 thr: col=t&15 -> hid ch [4c,4c+4), row=t>>4 -> 8 edges (4 f32x2 pairs)
__global__ __launch_bounds__(256, 2)
void scatter_kernel(const int* __restrict__ edge_index, const void* __restrict__ mask,
                    const float* __restrict__ edge_attr, const float* __restrict__ W_in) {
    extern __shared__ float smem[];
    float*  w_s    = smem;                         // [128][B_WS]  W_in^T k-major
    float*  x_s    = smem + 128 * B_WS;            // [128][B_XS]  attr^T k-major
    float4* coef_s = (float4*)(x_s + 128 * B_XS);  // dinv*(chr,chi,ctr,cti)
    int*    u_s    = (int*)(coef_s + 128);
    int*    v_s    = u_s + 128;

    const int t    = threadIdx.x;
    const int col  = t & 15;
    const int row  = t >> 4;
    const int mode = g_mask_mode;

    for (int idx = t; idx < 64 * 128; idx += 256) {       // stage W once per CTA
        int k = idx & 127, h = idx >> 7;
        w_s[k * B_WS + h] = W_in[h * 128 + k];
    }

    for (int tile = blockIdx.x; tile < NTILES; tile += gridDim.x) {
        __syncthreads();
        const int ebase = tile * 128;

        if (t < 128) {
            int e = ebase + t;
            int u = edge_index[e];
            int v = edge_index[NE + e];
            bool und = get_mask(mask, e, mode);
            float chr, chi, ctr, cti, dinv;
            if (und) { chr = 1.f;  chi = 0.f;   ctr = -1.f;  cti = 0.f;
                       dinv = (u == v) ? 0.f : RSQ2; }
            else     { chr = RSQ2; chi = -RSQ2; ctr = -RSQ2; cti = -RSQ2;
                       dinv = RSQ2; }
            u_s[t] = u; v_s[t] = v;
            coef_s[t] = make_float4(dinv * chr, dinv * chi, dinv * ctr, dinv * cti);
        }
        for (int idx = t; idx < 128 * 128; idx += 256) {  // attr^T tile
            int e = idx >> 7, k = idx & 127;
            x_s[k * B_XS + e] = edge_attr[(size_t)(ebase + e) * 128 + k];
        }
        __syncthreads();

        unsigned long long acc[4][4];
        #pragma unroll
        for (int p = 0; p < 4; p++) { acc[p][0]=0; acc[p][1]=0; acc[p][2]=0; acc[p][3]=0; }

        const float* wp  = w_s + 4 * col;
        const float* xp0 = x_s + row * 8;
        #pragma unroll 2
        for (int k = 0; k < 128; k++) {
            float4 w4 = *(const float4*)(wp + k * B_WS);
            unsigned long long w0 = pk2(w4.x, w4.x), w1 = pk2(w4.y, w4.y),
                               w2 = pk2(w4.z, w4.z), w3 = pk2(w4.w, w4.w);
            const unsigned long long* xq = (const unsigned long long*)(xp0 + k * B_XS);
            #pragma unroll
            for (int p = 0; p < 4; p++) {
                unsigned long long xv = xq[p];
                fma2(acc[p][0], xv, w0); fma2(acc[p][1], xv, w1);
                fma2(acc[p][2], xv, w2); fma2(acc[p][3], xv, w3);
            }
        }

        #pragma unroll
        for (int p = 0; p < 4; p++) {
            float2 z0 = upk2(acc[p][0]), z1 = upk2(acc[p][1]);
            float2 z2 = upk2(acc[p][2]), z3 = upk2(acc[p][3]);
            #pragma unroll
            for (int j = 0; j < 2; j++) {
                int el = row * 8 + 2 * p + j;
                float a0 = j ? z0.y : z0.x, a1 = j ? z1.y : z1.x;
                float a2 = j ? z2.y : z2.x, a3 = j ? z3.y : z3.x;
                float4 cf = coef_s[el];
                int u = u_s[el], v = v_s[el];
                // complex phase * z, channels (4c,4c+1)=c0, (4c+2,4c+3)=c1
                red4(&g_h[v * 64 + 4 * col],
                     cf.x * a0 - cf.y * a1, cf.x * a1 + cf.y * a0,
                     cf.x * a2 - cf.y * a3, cf.x * a3 + cf.y * a2);
                red4(&g_h[u * 64 + 4 * col],
                     cf.z * a0 - cf.w * a1, cf.z * a1 + cf.w * a0,
                     cf.z * a2 - cf.w * a3, cf.z * a3 + cf.w * a2);
            }
        }
    }
}

// ---------- pass 2: y = dinv*(conj phases . h) ; out = [y|attr]@Wcat^T + b ----------
// 256 thr: col=t&31 -> out ch [4c,4c+4), row=t>>5 -> 16 edges (8 f32x2 pairs)
__global__ __launch_bounds__(256, 1)
void gather_kernel(const int* __restrict__ edge_index, const void* __restrict__ mask,
                   const float* __restrict__ edge_attr,
                   const float* __restrict__ W_out, const float* __restrict__ W_skip,
                   const float* __restrict__ b_skip, const float* __restrict__ bias,
                   float* __restrict__ out) {
    extern __shared__ float smem[];
    float*  w_s    = smem;                         // [192][D_WS]  Wcat^T k-major
    float*  x_s    = smem + 192 * D_WS;            // [192][D_XS]  [y|attr]^T k-major
    float4* coef_s = (float4*)(x_s + 192 * D_XS);  // dinv*(ar,ai,br,bi)
    int*    u_s    = (int*)(coef_s + 128);
    int*    v_s    = u_s + 128;
    float*  bias_s = (float*)(v_s + 128);

    const int t    = threadIdx.x;
    const int col  = t & 31;
    const int row  = t >> 5;
    const int mode = g_mask_mode;

    // stage Wcat = [W_out (k<64) | W_skip (k>=64)] transposed, once per CTA
    for (int idx = t; idx < 192 * 128; idx += 256) {
        int c = idx / 192, k = idx - c * 192;
        float w = (k < 64) ? W_out[c * 64 + k] : W_skip[c * 128 + (k - 64)];
        w_s[k * D_WS + c] = w;
    }
    if (t < 128) bias_s[t] = b_skip[t] + bias[t];

    for (int tile = blockIdx.x; tile < NTILES; tile += gridDim.x) {
        __syncthreads();
        const int ebase = tile * 128;

        if (t < 128) {
            int e = ebase + t;
            int u = edge_index[e];
            int v = edge_index[NE + e];
            bool und = get_mask(mask, e, mode);
            float ar, ai, br, bi, dinv = RSQ2;
            if (und) { ar = 1.f;  ai = 0.f;   br = -1.f;  bi = 0.f;
                       if (u == v) dinv = 0.f; }
            else     { ar = RSQ2; ai = RSQ2;  br = -RSQ2; bi = RSQ2; }
            u_s[t] = u; v_s[t] = v;
            coef_s[t] = make_float4(dinv * ar, dinv * ai, dinv * br, dinv * bi);
        }
        __syncthreads();

        for (int idx = t; idx < 128 * 128; idx += 256) {  // attr^T into k rows [64,192)
            int e = idx >> 7, k = idx & 127;
            x_s[(64 + k) * D_XS + e] = edge_attr[(size_t)(ebase + e) * 128 + k];
        }
        for (int idx = t; idx < 128 * 32; idx += 256) {   // build y^T (k rows [0,64))
            int e = idx >> 5, p = idx & 31;
            int u = u_s[e], v = v_s[e];
            float4 cf = coef_s[e];
            float2 hv = *(const float2*)&g_h[v * 64 + 2 * p];
            float2 hu = *(const float2*)&g_h[u * 64 + 2 * p];
            float yr = cf.x * hv.x - cf.y * hv.y + cf.z * hu.x - cf.w * hu.y;
            float yi = cf.x * hv.y + cf.y * hv.x + cf.z * hu.y + cf.w * hu.x;
            x_s[(2 * p) * D_XS + e]     = yr;
            x_s[(2 * p + 1) * D_XS + e] = yi;
        }
        __syncthreads();

        unsigned long long acc[8][4];
        #pragma unroll
        for (int p = 0; p < 8; p++) { acc[p][0]=0; acc[p][1]=0; acc[p][2]=0; acc[p][3]=0; }

        const float* wp  = w_s + 4 * col;
        const float* xp0 = x_s + row * 16;
        #pragma unroll 2
        for (int k = 0; k < 192; k++) {
            float4 w4 = *(const float4*)(wp + k * D_WS);
            unsigned long long w0 = pk2(w4.x, w4.x), w1 = pk2(w4.y, w4.y),
                               w2 = pk2(w4.z, w4.z), w3 = pk2(w4.w, w4.w);
            const unsigned long long* xq = (const unsigned long long*)(xp0 + k * D_XS);
            #pragma unroll
            for (int p = 0; p < 8; p++) {
                unsigned long long xv = xq[p];
                fma2(acc[p][0], xv, w0); fma2(acc[p][1], xv, w1);
                fma2(acc[p][2], xv, w2); fma2(acc[p][3], xv, w3);
            }
        }

        float4 bia = *(const float4*)&bias_s[4 * col];
        #pragma unroll
        for (int p = 0; p < 8; p++) {
            float2 c0 = upk2(acc[p][0]), c1 = upk2(acc[p][1]);
            float2 c2 = upk2(acc[p][2]), c3 = upk2(acc[p][3]);
            size_t e0 = (size_t)(ebase + row * 16 + 2 * p);
            *(float4*)&out[e0 * 128 + 4 * col] =
                make_float4(c0.x + bia.x, c1.x + bia.y, c2.x + bia.z, c3.x + bia.w);
            *(float4*)&out[(e0 + 1) * 128 + 4 * col] =
                make_float4(c0.y + bia.x, c1.y + bia.y, c2.y + bia.z, c3.y + bia.w);
        }
    }
}

extern "C" void kernel_launch(void* const* d_in, const int* in_sizes, int n_in,
                              void* d_out, int out_size) {
    const int*   edge_index = (const int*)  d_in[0];
    const void*  mask       =               d_in[1];
    const float* edge_attr  = (const float*)d_in[2];
    const float* W_in       = (const float*)d_in[3];
    const float* W_out      = (const float*)d_in[4];
    const float* W_skip     = (const float*)d_in[5];
    const float* b_skip     = (const float*)d_in[6];
    const float* bias       = (const float*)d_in[7];
    float*       out        = (float*)d_out;

    cudaFuncSetAttribute(scatter_kernel, cudaFuncAttributeMaxDynamicSharedMemorySize, B_SMEM);
    cudaFuncSetAttribute(gather_kernel,  cudaFuncAttributeMaxDynamicSharedMemorySize, D_SMEM);

    probe_mask_kernel<<<1, 256>>>((const unsigned char*)mask);
    zero_h_kernel<<<148, 256>>>();
    scatter_kernel<<<296, 256, B_SMEM>>>(edge_index, mask, edge_attr, W_in);
    relu_h_kernel<<<148, 256>>>();
    gather_kernel<<<148, 256, D_SMEM>>>(edge_index, mask, edge_attr,
                                        W_out, W_skip, b_skip, bias, out);
}

// round 8
// speedup vs baseline: 1.8429x; 1.8429x over previous
#include <cuda_runtime.h>
#include <cuda_bf16.h>
#include <cstdint>

#define NE 800000
#define NN 50000
#define NTILES (NE/128)
#define RSQ2 0.70710678118654752440f

__device__ float g_h[NN * 64];
__device__ int   g_mask_mode;

// ---------------- helpers ----------------
static __device__ __forceinline__ uint32_t s2u(const void* p) {
    uint32_t a;
    asm("{ .reg .u64 t; cvta.to.shared.u64 t, %1; cvt.u32.u64 %0, t; }" : "=r"(a) : "l"(p));
    return a;
}
static __device__ __forceinline__ void ldsm4(uint32_t a, uint32_t r[4]) {
    asm volatile("ldmatrix.sync.aligned.m8n8.x4.shared.b16 {%0,%1,%2,%3}, [%4];"
                 : "=r"(r[0]), "=r"(r[1]), "=r"(r[2]), "=r"(r[3]) : "r"(a));
}
static __device__ __forceinline__ void ldsm2(uint32_t a, uint32_t r[2]) {
    asm volatile("ldmatrix.sync.aligned.m8n8.x2.shared.b16 {%0,%1}, [%2];"
                 : "=r"(r[0]), "=r"(r[1]) : "r"(a));
}
static __device__ __forceinline__ void mma16816(float c[4], const uint32_t a[4],
                                                const uint32_t b[2]) {
    asm volatile("mma.sync.aligned.m16n8k16.row.col.f32.bf16.bf16.f32 "
                 "{%0,%1,%2,%3}, {%4,%5,%6,%7}, {%8,%9}, {%0,%1,%2,%3};"
                 : "+f"(c[0]), "+f"(c[1]), "+f"(c[2]), "+f"(c[3])
                 : "r"(a[0]), "r"(a[1]), "r"(a[2]), "r"(a[3]), "r"(b[0]), "r"(b[1]));
}
static __device__ __forceinline__ void red4(float* p, float a, float b, float c, float d) {
    asm volatile("red.global.add.v4.f32 [%0], {%1, %2, %3, %4};"
                 :: "l"(p), "f"(a), "f"(b), "f"(c), "f"(d) : "memory");
}

// bf16 hi/lo split
static __device__ __forceinline__ void split1(float x, uint16_t& h, uint16_t& l) {
    __nv_bfloat16 hb = __float2bfloat16_rn(x);
    float r = x - __bfloat162float(hb);
    __nv_bfloat16 lb = __float2bfloat16_rn(r);
    h = __bfloat16_as_ushort(hb);
    l = __bfloat16_as_ushort(lb);
}
static __device__ __forceinline__ void cvt8(const float* x, uint4& hi, uint4& lo) {
    uint16_t h[8], l[8];
    #pragma unroll
    for (int i = 0; i < 8; i++) split1(x[i], h[i], l[i]);
    hi = make_uint4((uint32_t)h[0] | ((uint32_t)h[1] << 16), (uint32_t)h[2] | ((uint32_t)h[3] << 16),
                    (uint32_t)h[4] | ((uint32_t)h[5] << 16), (uint32_t)h[6] | ((uint32_t)h[7] << 16));
    lo = make_uint4((uint32_t)l[0] | ((uint32_t)l[1] << 16), (uint32_t)l[2] | ((uint32_t)l[3] << 16),
                    (uint32_t)l[4] | ((uint32_t)l[5] << 16), (uint32_t)l[6] | ((uint32_t)l[7] << 16));
}

// ---------------- mask dtype ----------------
static __device__ __forceinline__ bool get_mask(const void* m, int e, int mode) {
    if (mode == 0) return ((const int*)m)[e] != 0;
    if (mode == 1) return ((const unsigned char*)m)[e] != 0;
    return ((const float*)m)[e] != 0.0f;
}
__global__ void probe_mask_kernel(const unsigned char* __restrict__ m) {
    __shared__ int flag[4];
    int t = threadIdx.x;
    if (t < 4) flag[t] = 0;
    __syncthreads();
    int any = 0;
    for (int i = t; i < 4096; i += 256) any |= (int)m[i];
    if (any) atomicOr(&flag[t & 3], 1);
    __syncthreads();
    if (t == 0) {
        int mode;
        if (flag[1] || (flag[0] && (flag[2] | flag[3]))) mode = 1;   // u8/bool
        else if (flag[2] | flag[3])                      mode = 2;   // f32
        else                                             mode = 0;   // i32
        g_mask_mode = mode;
    }
}

__global__ void zero_h_kernel() {
    float4* p = (float4*)g_h;
    const int n = NN * 64 / 4;
    for (int i = blockIdx.x * blockDim.x + threadIdx.x; i < n; i += gridDim.x * blockDim.x)
        p[i] = make_float4(0.f, 0.f, 0.f, 0.f);
}
__global__ void relu_h_kernel() {
    float4* p = (float4*)g_h;
    const int n = NN * 64 / 4;
    for (int i = blockIdx.x * blockDim.x + threadIdx.x; i < n; i += gridDim.x * blockDim.x) {
        float4 v = p[i];
        v.x = fmaxf(v.x, 0.f); v.y = fmaxf(v.y, 0.f);
        v.z = fmaxf(v.z, 0.f); v.w = fmaxf(v.w, 0.f);
        p[i] = v;
    }
}

// ---------------- scatter: z = (attr @ W_in^T)*dinv ; phase*z -> g_h ----------------
// smem (bytes): Whi[64][136]h, Wlo, Ahi[128][136]h, Alo, coef f4[128], u[128], v[128]
#define SC_WH 0
#define SC_WL 17408
#define SC_AH 34816
#define SC_AL 69632
#define SC_CF 104448
#define SC_U  106496
#define SC_V  107008
#define SC_SMEM 107520

__global__ __launch_bounds__(256, 2)
void scatter_kernel(const int* __restrict__ ei, const void* __restrict__ mask,
                    const float* __restrict__ attr, const float* __restrict__ W_in) {
    extern __shared__ char sm[];
    const uint32_t sb = s2u(sm);
    const int t = threadIdx.x, w = t >> 5, lane = t & 31;
    const int mode = g_mask_mode;

    // stage W_in [64 x 128] once (hi/lo, padded rows of 136 halves)
    for (int g = t; g < 1024; g += 256) {
        int row = g >> 4, k0 = (g & 15) * 8;
        float x[8];
        *(float4*)&x[0] = *(const float4*)(W_in + row * 128 + k0);
        *(float4*)&x[4] = *(const float4*)(W_in + row * 128 + k0 + 4);
        uint4 hi, lo; cvt8(x, hi, lo);
        *(uint4*)(sm + SC_WH + (row * 136 + k0) * 2) = hi;
        *(uint4*)(sm + SC_WL + (row * 136 + k0) * 2) = lo;
    }
    __syncthreads();

    // resident B fragments: warp w owns hid cols [8w, 8w+8)
    uint32_t bh[8][2], bl[8][2];
    {
        uint32_t ro = (uint32_t)(8 * w + (lane & 7)) * 272;  // *136 halves *2B
        #pragma unroll
        for (int ks = 0; ks < 8; ks++) {
            uint32_t co = (uint32_t)(ks * 16 + (lane & 8)) * 2;
            ldsm2(sb + SC_WH + ro + co, bh[ks]);
            ldsm2(sb + SC_WL + ro + co, bl[ks]);
        }
    }
    float4* coef_s = (float4*)(sm + SC_CF);
    int*    u_s    = (int*)(sm + SC_U);
    int*    v_s    = (int*)(sm + SC_V);

    const int n0 = 8 * w, g4 = lane >> 2, t4 = lane & 3, col = n0 + 2 * t4;

    for (int tile = blockIdx.x; tile < NTILES; tile += gridDim.x) {
        __syncthreads();
        const int eb = tile * 128;
        if (t < 128) {
            int e = eb + t;
            int u = ei[e], v = ei[NE + e];
            bool und = get_mask(mask, e, mode);
            float chr, chi, ctr, cti, dinv;
            if (und) { chr = 1.f;  chi = 0.f;   ctr = -1.f;  cti = 0.f;
                       dinv = (u == v) ? 0.f : RSQ2; }
            else     { chr = RSQ2; chi = -RSQ2; ctr = -RSQ2; cti = -RSQ2; dinv = RSQ2; }
            u_s[t] = u; v_s[t] = v;
            coef_s[t] = make_float4(dinv * chr, dinv * chi, dinv * ctr, dinv * cti);
        }
        for (int g = t; g < 2048; g += 256) {           // A tile (hi/lo)
            int row = g >> 4, k0 = (g & 15) * 8;
            float x[8];
            const float* ap = attr + (size_t)(eb + row) * 128 + k0;
            *(float4*)&x[0] = *(const float4*)ap;
            *(float4*)&x[4] = *(const float4*)(ap + 4);
            uint4 hi, lo; cvt8(x, hi, lo);
            *(uint4*)(sm + SC_AH + (row * 136 + k0) * 2) = hi;
            *(uint4*)(sm + SC_AL + (row * 136 + k0) * 2) = lo;
        }
        __syncthreads();

        #pragma unroll 1
        for (int mt = 0; mt < 8; mt++) {
            const int m0 = mt * 16;
            float c[4] = {0.f, 0.f, 0.f, 0.f};
            uint32_t arow  = (uint32_t)(m0 + (lane & 15)) * 272;
            uint32_t acol0 = (uint32_t)((lane >> 4) << 4);
            #pragma unroll
            for (int ks = 0; ks < 8; ks++) {
                uint32_t ao = arow + ks * 32 + acol0;
                uint32_t ah[4], al[4];
                ldsm4(sb + SC_AH + ao, ah);
                ldsm4(sb + SC_AL + ao, al);
                mma16816(c, ah, bh[ks]);   // hi*hi
                mma16816(c, ah, bl[ks]);   // hi*lo
                mma16816(c, al, bh[ks]);   // lo*hi
            }
            // epilogue: rows g4 and g4+8; lane-pair swap -> 16B vector atomics
            #pragma unroll
            for (int rr = 0; rr < 2; rr++) {
                int el = m0 + g4 + rr * 8;
                float re = rr ? c[2] : c[0], im = rr ? c[3] : c[1];
                float4 cf = coef_s[el];
                int u = u_s[el], v = v_s[el];
                float hvx = cf.x * re - cf.y * im, hvy = cf.x * im + cf.y * re;
                float hux = cf.z * re - cf.w * im, huy = cf.z * im + cf.w * re;
                float pvx = __shfl_xor_sync(0xffffffffu, hvx, 1);
                float pvy = __shfl_xor_sync(0xffffffffu, hvy, 1);
                float pux = __shfl_xor_sync(0xffffffffu, hux, 1);
                float puy = __shfl_xor_sync(0xffffffffu, huy, 1);
                if (t4 & 1) red4(&g_h[(size_t)u * 64 + col - 2], pux, puy, hux, huy);
                else        red4(&g_h[(size_t)v * 64 + col],     hvx, hvy, pvx, pvy);
            }
        }
    }
}

// ---------------- gather: y = dinv*(conj-phase . h) ; out = [y|attr]@Wcat^T + b ----------------
// smem: Whi[128][200]h, Wlo, Ahi[128][200]h, Alo, coef, u, v, bias
#define GA_WH 0
#define GA_WL 51200
#define GA_AH 102400
#define GA_AL 153600
#define GA_CF 204800
#define GA_U  206848
#define GA_V  207360
#define GA_BI 207872
#define GA_SMEM 208384

__global__ __launch_bounds__(256, 1)
void gather_kernel(const int* __restrict__ ei, const void* __restrict__ mask,
                   const float* __restrict__ attr,
                   const float* __restrict__ W_out, const float* __restrict__ W_skip,
                   const float* __restrict__ b_skip, const float* __restrict__ bias,
                   float* __restrict__ out) {
    extern __shared__ char sm[];
    const uint32_t sb = s2u(sm);
    const int t = threadIdx.x, w = t >> 5, lane = t & 31;
    const int mode = g_mask_mode;

    // stage Wcat [128 x 192] once: k<64 -> W_out, else W_skip
    for (int g = t; g < 3072; g += 256) {
        int row = g / 24, k0 = (g % 24) * 8;
        float x[8];
        if (k0 < 64) {
            *(float4*)&x[0] = *(const float4*)(W_out + row * 64 + k0);
            *(float4*)&x[4] = *(const float4*)(W_out + row * 64 + k0 + 4);
        } else {
            *(float4*)&x[0] = *(const float4*)(W_skip + row * 128 + (k0 - 64));
            *(float4*)&x[4] = *(const float4*)(W_skip + row * 128 + (k0 - 64) + 4);
        }
        uint4 hi, lo; cvt8(x, hi, lo);
        *(uint4*)(sm + GA_WH + (row * 200 + k0) * 2) = hi;
        *(uint4*)(sm + GA_WL + (row * 200 + k0) * 2) = lo;
    }
    if (t < 128) ((float*)(sm + GA_BI))[t] = b_skip[t] + bias[t];
    __syncthreads();

    // resident B fragments: warp w owns out cols [8w,8w+8) and [64+8w, 64+8w+8)
    uint32_t bh[2][12][2], bl[2][12][2];
    #pragma unroll
    for (int s = 0; s < 2; s++) {
        uint32_t ro = (uint32_t)(s * 64 + 8 * w + (lane & 7)) * 400;  // *200h*2B
        #pragma unroll
        for (int ks = 0; ks < 12; ks++) {
            uint32_t co = (uint32_t)(ks * 16 + (lane & 8)) * 2;
            ldsm2(sb + GA_WH + ro + co, bh[s][ks]);
            ldsm2(sb + GA_WL + ro + co, bl[s][ks]);
        }
    }
    float4* coef_s = (float4*)(sm + GA_CF);
    int*    u_s    = (int*)(sm + GA_U);
    int*    v_s    = (int*)(sm + GA_V);

    const int g4 = lane >> 2, t4 = lane & 3;
    float2 b2[2];
    b2[0] = *(float2*)(sm + GA_BI + (8 * w + 2 * t4) * 4);
    b2[1] = *(float2*)(sm + GA_BI + (64 + 8 * w + 2 * t4) * 4);

    for (int tile = blockIdx.x; tile < NTILES; tile += gridDim.x) {
        __syncthreads();
        const int eb = tile * 128;
        if (t < 128) {
            int e = eb + t;
            int u = ei[e], v = ei[NE + e];
            bool und = get_mask(mask, e, mode);
            float ar, ai, br, bi, dinv = RSQ2;
            if (und) { ar = 1.f;  ai = 0.f;  br = -1.f;  bi = 0.f;
                       if (u == v) dinv = 0.f; }
            else     { ar = RSQ2; ai = RSQ2; br = -RSQ2; bi = RSQ2; }
            u_s[t] = u; v_s[t] = v;
            coef_s[t] = make_float4(dinv * ar, dinv * ai, dinv * br, dinv * bi);
        }
        for (int g = t; g < 2048; g += 256) {          // attr -> k rows [64,192)
            int row = g >> 4, k0 = (g & 15) * 8;
            float x[8];
            const float* ap = attr + (size_t)(eb + row) * 128 + k0;
            *(float4*)&x[0] = *(const float4*)ap;
            *(float4*)&x[4] = *(const float4*)(ap + 4);
            uint4 hi, lo; cvt8(x, hi, lo);
            *(uint4*)(sm + GA_AH + (row * 200 + 64 + k0) * 2) = hi;
            *(uint4*)(sm + GA_AL + (row * 200 + 64 + k0) * 2) = lo;
        }
        __syncthreads();                                // coefs ready
        for (int g = t; g < 4096; g += 256) {           // y -> k rows [0,64)
            int e = g >> 5, p = g & 31;
            int u = u_s[e], v = v_s[e];
            float4 cf = coef_s[e];
            float2 hv = *(const float2*)&g_h[(size_t)v * 64 + 2 * p];
            float2 hu = *(const float2*)&g_h[(size_t)u * 64 + 2 * p];
            float yr = cf.x * hv.x - cf.y * hv.y + cf.z * hu.x - cf.w * hu.y;
            float yi = cf.x * hv.y + cf.y * hv.x + cf.z * hu.y + cf.w * hu.x;
            uint16_t hr, lr, hi_, li;
            split1(yr, hr, lr); split1(yi, hi_, li);
            *(uint32_t*)(sm + GA_AH + e * 400 + 4 * p) = (uint32_t)hr | ((uint32_t)hi_ << 16);
            *(uint32_t*)(sm + GA_AL + e * 400 + 4 * p) = (uint32_t)lr | ((uint32_t)li << 16);
        }
        __syncthreads();

        #pragma unroll 1
        for (int mt = 0; mt < 8; mt++) {
            const int m0 = mt * 16;
            float c0[4] = {0.f, 0.f, 0.f, 0.f};
            float c1[4] = {0.f, 0.f, 0.f, 0.f};
            uint32_t arow  = (uint32_t)(m0 + (lane & 15)) * 400;
            uint32_t acol0 = (uint32_t)((lane >> 4) << 4);
            #pragma unroll
            for (int ks = 0; ks < 12; ks++) {
                uint32_t ao = arow + ks * 32 + acol0;
                uint32_t ah[4], al[4];
                ldsm4(sb + GA_AH + ao, ah);
                ldsm4(sb + GA_AL + ao, al);
                mma16816(c0, ah, bh[0][ks]);
                mma16816(c0, ah, bl[0][ks]);
                mma16816(c0, al, bh[0][ks]);
                mma16816(c1, ah, bh[1][ks]);
                mma16816(c1, ah, bl[1][ks]);
                mma16816(c1, al, bh[1][ks]);
            }
            int e0 = eb + m0 + g4;
            int ca = 8 * w + 2 * t4, cb = 64 + 8 * w + 2 * t4;
            *(float2*)&out[(size_t)e0 * 128 + ca] = make_float2(c0[0] + b2[0].x, c0[1] + b2[0].y);
            *(float2*)&out[(size_t)(e0 + 8) * 128 + ca] = make_float2(c0[2] + b2[0].x, c0[3] + b2[0].y);
            *(float2*)&out[(size_t)e0 * 128 + cb] = make_float2(c1[0] + b2[1].x, c1[1] + b2[1].y);
            *(float2*)&out[(size_t)(e0 + 8) * 128 + cb] = make_float2(c1[2] + b2[1].x, c1[3] + b2[1].y);
        }
    }
}

extern "C" void kernel_launch(void* const* d_in, const int* in_sizes, int n_in,
                              void* d_out, int out_size) {
    const int*   edge_index = (const int*)  d_in[0];
    const void*  mask       =               d_in[1];
    const float* edge_attr  = (const float*)d_in[2];
    const float* W_in       = (const float*)d_in[3];
    const float* W_out      = (const float*)d_in[4];
    const float* W_skip     = (const float*)d_in[5];
    const float* b_skip     = (const float*)d_in[6];
    const float* bias       = (const float*)d_in[7];
    float*       out        = (float*)d_out;

    cudaFuncSetAttribute(scatter_kernel, cudaFuncAttributeMaxDynamicSharedMemorySize, SC_SMEM);
    cudaFuncSetAttribute(gather_kernel,  cudaFuncAttributeMaxDynamicSharedMemorySize, GA_SMEM);

    probe_mask_kernel<<<1, 256>>>((const unsigned char*)mask);
    zero_h_kernel<<<148, 256>>>();
    scatter_kernel<<<296, 256, SC_SMEM>>>(edge_index, mask, edge_attr, W_in);
    relu_h_kernel<<<148, 256>>>();
    gather_kernel<<<148, 256, GA_SMEM>>>(edge_index, mask, edge_attr,
                                         W_out, W_skip, b_skip, bias, out);
}

// round 9
// speedup vs baseline: 2.5567x; 1.3873x over previous
#include <cuda_runtime.h>
#include <cuda_fp16.h>
#include <cstdint>

#define NE 800000
#define NN 50000
#define NTILES (NE/128)
#define RSQ2 0.70710678118654752440f

__device__ float g_h[NN * 64];
__device__ int   g_mask_mode;

// ---------------- helpers ----------------
static __device__ __forceinline__ uint32_t s2u(const void* p) {
    uint32_t a;
    asm("{ .reg .u64 t; cvta.to.shared.u64 t, %1; cvt.u32.u64 %0, t; }" : "=r"(a) : "l"(p));
    return a;
}
static __device__ __forceinline__ void ldsm4(uint32_t a, uint32_t r[4]) {
    asm volatile("ldmatrix.sync.aligned.m8n8.x4.shared.b16 {%0,%1,%2,%3}, [%4];"
                 : "=r"(r[0]), "=r"(r[1]), "=r"(r[2]), "=r"(r[3]) : "r"(a));
}
static __device__ __forceinline__ void ldsm2(uint32_t a, uint32_t r[2]) {
    asm volatile("ldmatrix.sync.aligned.m8n8.x2.shared.b16 {%0,%1}, [%2];"
                 : "=r"(r[0]), "=r"(r[1]) : "r"(a));
}
static __device__ __forceinline__ void mma16816(float c[4], const uint32_t a[4],
                                                const uint32_t b[2]) {
    asm volatile("mma.sync.aligned.m16n8k16.row.col.f32.f16.f16.f32 "
                 "{%0,%1,%2,%3}, {%4,%5,%6,%7}, {%8,%9}, {%0,%1,%2,%3};"
                 : "+f"(c[0]), "+f"(c[1]), "+f"(c[2]), "+f"(c[3])
                 : "r"(a[0]), "r"(a[1]), "r"(a[2]), "r"(a[3]), "r"(b[0]), "r"(b[1]));
}
static __device__ __forceinline__ void red4(float* p, float a, float b, float c, float d) {
    asm volatile("red.global.add.v4.f32 [%0], {%1, %2, %3, %4};"
                 :: "l"(p), "f"(a), "f"(b), "f"(c), "f"(d) : "memory");
}
static __device__ __forceinline__ uint32_t f2h2(float a, float b) {
    __half2 h = __floats2half2_rn(a, b);
    return *(uint32_t*)&h;
}
static __device__ __forceinline__ void cvt8h(const float* x, uint4& o) {
    o = make_uint4(f2h2(x[0], x[1]), f2h2(x[2], x[3]),
                   f2h2(x[4], x[5]), f2h2(x[6], x[7]));
}
// weights: fp16 hi + fp16 residual (staged once; makes B-side exact to ~2^-22)
static __device__ __forceinline__ void wsplit8(const float* x, uint4& hi, uint4& lo) {
    uint16_t hh[8]; float r[8];
    #pragma unroll
    for (int i = 0; i < 8; i++) {
        __half h = __float2half_rn(x[i]);
        hh[i] = __half_as_ushort(h);
        r[i] = x[i] - __half2float(h);
    }
    hi = make_uint4((uint32_t)hh[0] | ((uint32_t)hh[1] << 16),
                    (uint32_t)hh[2] | ((uint32_t)hh[3] << 16),
                    (uint32_t)hh[4] | ((uint32_t)hh[5] << 16),
                    (uint32_t)hh[6] | ((uint32_t)hh[7] << 16));
    lo = make_uint4(f2h2(r[0], r[1]), f2h2(r[2], r[3]),
                    f2h2(r[4], r[5]), f2h2(r[6], r[7]));
}

// ---------------- mask dtype ----------------
static __device__ __forceinline__ bool get_mask(const void* m, int e, int mode) {
    if (mode == 0) return ((const int*)m)[e] != 0;
    if (mode == 1) return ((const unsigned char*)m)[e] != 0;
    return ((const float*)m)[e] != 0.0f;
}
__global__ void probe_mask_kernel(const unsigned char* __restrict__ m) {
    __shared__ int flag[4];
    int t = threadIdx.x;
    if (t < 4) flag[t] = 0;
    __syncthreads();
    int any = 0;
    for (int i = t; i < 4096; i += 256) any |= (int)m[i];
    if (any) atomicOr(&flag[t & 3], 1);
    __syncthreads();
    if (t == 0) {
        int mode;
        if (flag[1] || (flag[0] && (flag[2] | flag[3]))) mode = 1;   // u8/bool
        else if (flag[2] | flag[3])                      mode = 2;   // f32
        else                                             mode = 0;   // i32
        g_mask_mode = mode;
    }
}

__global__ void zero_h_kernel() {
    float4* p = (float4*)g_h;
    const int n = NN * 64 / 4;
    for (int i = blockIdx.x * blockDim.x + threadIdx.x; i < n; i += gridDim.x * blockDim.x)
        p[i] = make_float4(0.f, 0.f, 0.f, 0.f);
}
__global__ void relu_h_kernel() {
    float4* p = (float4*)g_h;
    const int n = NN * 64 / 4;
    for (int i = blockIdx.x * blockDim.x + threadIdx.x; i < n; i += gridDim.x * blockDim.x) {
        float4 v = p[i];
        v.x = fmaxf(v.x, 0.f); v.y = fmaxf(v.y, 0.f);
        v.z = fmaxf(v.z, 0.f); v.w = fmaxf(v.w, 0.f);
        p[i] = v;
    }
}

// ---------------- scatter: z = (attr @ W_in^T)*dinv ; phase*z -> g_h ----------------
// smem: Whi[64][136]h, Wlo, A[128][136]h, coef f4[128], u[128], v[128]
#define SC_WH 0
#define SC_WL 17408
#define SC_A  34816
#define SC_CF 69632
#define SC_U  71680
#define SC_V  72192
#define SC_SMEM 72704

__global__ __launch_bounds__(256, 3)
void scatter_kernel(const int* __restrict__ ei, const void* __restrict__ mask,
                    const float* __restrict__ attr, const float* __restrict__ W_in) {
    extern __shared__ char sm[];
    const uint32_t sb = s2u(sm);
    const int t = threadIdx.x, w = t >> 5, lane = t & 31;
    const int mode = g_mask_mode;

    // stage W_in [64 x 128] once (fp16 hi/lo, padded rows of 136 halves)
    for (int g = t; g < 1024; g += 256) {
        int row = g >> 4, k0 = (g & 15) * 8;
        float x[8];
        *(float4*)&x[0] = *(const float4*)(W_in + row * 128 + k0);
        *(float4*)&x[4] = *(const float4*)(W_in + row * 128 + k0 + 4);
        uint4 hi, lo; wsplit8(x, hi, lo);
        *(uint4*)(sm + SC_WH + (row * 136 + k0) * 2) = hi;
        *(uint4*)(sm + SC_WL + (row * 136 + k0) * 2) = lo;
    }
    __syncthreads();

    // resident B fragments: warp w owns hid cols [8w, 8w+8)
    uint32_t bh[8][2], bl[8][2];
    {
        uint32_t ro = (uint32_t)(8 * w + (lane & 7)) * 272;
        #pragma unroll
        for (int ks = 0; ks < 8; ks++) {
            uint32_t co = (uint32_t)(ks * 16 + (lane & 8)) * 2;
            ldsm2(sb + SC_WH + ro + co, bh[ks]);
            ldsm2(sb + SC_WL + ro + co, bl[ks]);
        }
    }
    float4* coef_s = (float4*)(sm + SC_CF);
    int*    u_s    = (int*)(sm + SC_U);
    int*    v_s    = (int*)(sm + SC_V);

    const int n0 = 8 * w, g4 = lane >> 2, t4 = lane & 3, col = n0 + 2 * t4;

    for (int tile = blockIdx.x; tile < NTILES; tile += gridDim.x) {
        __syncthreads();
        const int eb = tile * 128;
        if (t < 128) {
            int e = eb + t;
            int u = ei[e], v = ei[NE + e];
            bool und = get_mask(mask, e, mode);
            float chr, chi, ctr, cti, dinv;
            if (und) { chr = 1.f;  chi = 0.f;   ctr = -1.f;  cti = 0.f;
                       dinv = (u == v) ? 0.f : RSQ2; }
            else     { chr = RSQ2; chi = -RSQ2; ctr = -RSQ2; cti = -RSQ2; dinv = RSQ2; }
            u_s[t] = u; v_s[t] = v;
            coef_s[t] = make_float4(dinv * chr, dinv * chi, dinv * ctr, dinv * cti);
        }
        for (int g = t; g < 2048; g += 256) {           // A tile (single fp16)
            int row = g >> 4, k0 = (g & 15) * 8;
            float x[8];
            const float* ap = attr + (size_t)(eb + row) * 128 + k0;
            *(float4*)&x[0] = *(const float4*)ap;
            *(float4*)&x[4] = *(const float4*)(ap + 4);
            uint4 av; cvt8h(x, av);
            *(uint4*)(sm + SC_A + (row * 136 + k0) * 2) = av;
        }
        __syncthreads();

        #pragma unroll 1
        for (int mt = 0; mt < 8; mt++) {
            const int m0 = mt * 16;
            float c[4] = {0.f, 0.f, 0.f, 0.f};
            uint32_t arow  = (uint32_t)(m0 + (lane & 15)) * 272;
            uint32_t acol0 = (uint32_t)((lane >> 4) << 4);
            #pragma unroll
            for (int ks = 0; ks < 8; ks++) {
                uint32_t a4[4];
                ldsm4(sb + SC_A + arow + ks * 32 + acol0, a4);
                mma16816(c, a4, bh[ks]);   // a * w_hi
                mma16816(c, a4, bl[ks]);   // a * w_lo
            }
            #pragma unroll
            for (int rr = 0; rr < 2; rr++) {
                int el = m0 + g4 + rr * 8;
                float re = rr ? c[2] : c[0], im = rr ? c[3] : c[1];
                float4 cf = coef_s[el];
                int u = u_s[el], v = v_s[el];
                float hvx = cf.x * re - cf.y * im, hvy = cf.x * im + cf.y * re;
                float hux = cf.z * re - cf.w * im, huy = cf.z * im + cf.w * re;
                float pvx = __shfl_xor_sync(0xffffffffu, hvx, 1);
                float pvy = __shfl_xor_sync(0xffffffffu, hvy, 1);
                float pux = __shfl_xor_sync(0xffffffffu, hux, 1);
                float puy = __shfl_xor_sync(0xffffffffu, huy, 1);
                if (t4 & 1) red4(&g_h[(size_t)u * 64 + col - 2], pux, puy, hux, huy);
                else        red4(&g_h[(size_t)v * 64 + col],     hvx, hvy, pvx, pvy);
            }
        }
    }
}

// ---------------- gather: y = dinv*(conj-phase . h) ; out = [y|attr]@Wcat^T + b ----------------
// smem: Whi[128][200]h, Wlo, A[128][200]h, coef, u, v, bias
#define GA_WH 0
#define GA_WL 51200
#define GA_A  102400
#define GA_CF 153600
#define GA_U  155648
#define GA_V  156160
#define GA_BI 156672
#define GA_SMEM 157184

__global__ __launch_bounds__(512, 1)
void gather_kernel(const int* __restrict__ ei, const void* __restrict__ mask,
                   const float* __restrict__ attr,
                   const float* __restrict__ W_out, const float* __restrict__ W_skip,
                   const float* __restrict__ b_skip, const float* __restrict__ bias,
                   float* __restrict__ out) {
    extern __shared__ char sm[];
    const uint32_t sb = s2u(sm);
    const int t = threadIdx.x, w = t >> 5, lane = t & 31;
    const int mode = g_mask_mode;

    // stage Wcat [128 x 192] once: k<64 -> W_out, else W_skip (fp16 hi/lo)
    for (int g = t; g < 3072; g += 512) {
        int row = g / 24, k0 = (g % 24) * 8;
        float x[8];
        if (k0 < 64) {
            *(float4*)&x[0] = *(const float4*)(W_out + row * 64 + k0);
            *(float4*)&x[4] = *(const float4*)(W_out + row * 64 + k0 + 4);
        } else {
            *(float4*)&x[0] = *(const float4*)(W_skip + row * 128 + (k0 - 64));
            *(float4*)&x[4] = *(const float4*)(W_skip + row * 128 + (k0 - 64) + 4);
        }
        uint4 hi, lo; wsplit8(x, hi, lo);
        *(uint4*)(sm + GA_WH + (row * 200 + k0) * 2) = hi;
        *(uint4*)(sm + GA_WL + (row * 200 + k0) * 2) = lo;
    }
    if (t < 128) ((float*)(sm + GA_BI))[t] = b_skip[t] + bias[t];
    __syncthreads();

    // resident B fragments: warp w (16 warps) owns out cols [8w, 8w+8)
    uint32_t bh[12][2], bl[12][2];
    {
        uint32_t ro = (uint32_t)(8 * w + (lane & 7)) * 400;
        #pragma unroll
        for (int ks = 0; ks < 12; ks++) {
            uint32_t co = (uint32_t)(ks * 16 + (lane & 8)) * 2;
            ldsm2(sb + GA_WH + ro + co, bh[ks]);
            ldsm2(sb + GA_WL + ro + co, bl[ks]);
        }
    }
    float4* coef_s = (float4*)(sm + GA_CF);
    int*    u_s    = (int*)(sm + GA_U);
    int*    v_s    = (int*)(sm + GA_V);

    const int g4 = lane >> 2, t4 = lane & 3;
    float2 b2 = *(float2*)(sm + GA_BI + (8 * w + 2 * t4) * 4);

    for (int tile = blockIdx.x; tile < NTILES; tile += gridDim.x) {
        __syncthreads();
        const int eb = tile * 128;
        if (t < 128) {
            int e = eb + t;
            int u = ei[e], v = ei[NE + e];
            bool und = get_mask(mask, e, mode);
            float ar, ai, br, bi, dinv = RSQ2;
            if (und) { ar = 1.f;  ai = 0.f;  br = -1.f;  bi = 0.f;
                       if (u == v) dinv = 0.f; }
            else     { ar = RSQ2; ai = RSQ2; br = -RSQ2; bi = RSQ2; }
            u_s[t] = u; v_s[t] = v;
            coef_s[t] = make_float4(dinv * ar, dinv * ai, dinv * br, dinv * bi);
        }
        for (int g = t; g < 2048; g += 512) {           // attr -> k rows [64,192)
            int row = g >> 4, k0 = (g & 15) * 8;
            float x[8];
            const float* ap = attr + (size_t)(eb + row) * 128 + k0;
            *(float4*)&x[0] = *(const float4*)ap;
            *(float4*)&x[4] = *(const float4*)(ap + 4);
            uint4 av; cvt8h(x, av);
            *(uint4*)(sm + GA_A + (row * 200 + 64 + k0) * 2) = av;
        }
        __syncthreads();                                // coefs ready
        for (int g = t; g < 4096; g += 512) {           // y -> k rows [0,64)
            int e = g >> 5, p = g & 31;
            int u = u_s[e], v = v_s[e];
            float4 cf = coef_s[e];
            float2 hv = *(const float2*)&g_h[(size_t)v * 64 + 2 * p];
            float2 hu = *(const float2*)&g_h[(size_t)u * 64 + 2 * p];
            float yr = cf.x * hv.x - cf.y * hv.y + cf.z * hu.x - cf.w * hu.y;
            float yi = cf.x * hv.y + cf.y * hv.x + cf.z * hu.y + cf.w * hu.x;
            *(uint32_t*)(sm + GA_A + e * 400 + 4 * p) = f2h2(yr, yi);
        }
        __syncthreads();

        #pragma unroll 1
        for (int mt = 0; mt < 8; mt++) {
            const int m0 = mt * 16;
            float c[4] = {0.f, 0.f, 0.f, 0.f};
            uint32_t arow  = (uint32_t)(m0 + (lane & 15)) * 400;
            uint32_t acol0 = (uint32_t)((lane >> 4) << 4);
            #pragma unroll
            for (int ks = 0; ks < 12; ks++) {
                uint32_t a4[4];
                ldsm4(sb + GA_A + arow + ks * 32 + acol0, a4);
                mma16816(c, a4, bh[ks]);
                mma16816(c, a4, bl[ks]);
            }
            int e0 = eb + m0 + g4;
            int ca = 8 * w + 2 * t4;
            *(float2*)&out[(size_t)e0 * 128 + ca] =
                make_float2(c[0] + b2.x, c[1] + b2.y);
            *(float2*)&out[(size_t)(e0 + 8) * 128 + ca] =
                make_float2(c[2] + b2.x, c[3] + b2.y);
        }
    }
}

extern "C" void kernel_launch(void* const* d_in, const int* in_sizes, int n_in,
                              void* d_out, int out_size) {
    const int*   edge_index = (const int*)  d_in[0];
    const void*  mask       =               d_in[1];
    const float* edge_attr  = (const float*)d_in[2];
    const float* W_in       = (const float*)d_in[3];
    const float* W_out      = (const float*)d_in[4];
    const float* W_skip     = (const float*)d_in[5];
    const float* b_skip     = (const float*)d_in[6];
    const float* bias       = (const float*)d_in[7];
    float*       out        = (float*)d_out;

    cudaFuncSetAttribute(scatter_kernel, cudaFuncAttributeMaxDynamicSharedMemorySize, SC_SMEM);
    cudaFuncSetAttribute(gather_kernel,  cudaFuncAttributeMaxDynamicSharedMemorySize, GA_SMEM);

    probe_mask_kernel<<<1, 256>>>((const unsigned char*)mask);
    zero_h_kernel<<<148, 256>>>();
    scatter_kernel<<<444, 256, SC_SMEM>>>(edge_index, mask, edge_attr, W_in);
    relu_h_kernel<<<148, 256>>>();
    gather_kernel<<<148, 512, GA_SMEM>>>(edge_index, mask, edge_attr,
                                         W_out, W_skip, b_skip, bias, out);
}

// round 10
// speedup vs baseline: 2.6540x; 1.0381x over previous
#include <cuda_runtime.h>
#include <cuda_fp16.h>
#include <cstdint>

#define NE 800000
#define NN 50000
#define NTILES (NE/128)
#define RSQ2 0.70710678118654752440f

__device__ float g_h[NN * 64];
__device__ int   g_mask_mode;

// ---------------- helpers ----------------
static __device__ __forceinline__ uint32_t s2u(const void* p) {
    uint32_t a;
    asm("{ .reg .u64 t; cvta.to.shared.u64 t, %1; cvt.u32.u64 %0, t; }" : "=r"(a) : "l"(p));
    return a;
}
static __device__ __forceinline__ void ldsm4(uint32_t a, uint32_t r[4]) {
    asm volatile("ldmatrix.sync.aligned.m8n8.x4.shared.b16 {%0,%1,%2,%3}, [%4];"
                 : "=r"(r[0]), "=r"(r[1]), "=r"(r[2]), "=r"(r[3]) : "r"(a));
}
static __device__ __forceinline__ void ldsm2(uint32_t a, uint32_t r[2]) {
    asm volatile("ldmatrix.sync.aligned.m8n8.x2.shared.b16 {%0,%1}, [%2];"
                 : "=r"(r[0]), "=r"(r[1]) : "r"(a));
}
static __device__ __forceinline__ void mma16816(float c[4], const uint32_t a[4],
                                                const uint32_t b[2]) {
    asm volatile("mma.sync.aligned.m16n8k16.row.col.f32.f16.f16.f32 "
                 "{%0,%1,%2,%3}, {%4,%5,%6,%7}, {%8,%9}, {%0,%1,%2,%3};"
                 : "+f"(c[0]), "+f"(c[1]), "+f"(c[2]), "+f"(c[3])
                 : "r"(a[0]), "r"(a[1]), "r"(a[2]), "r"(a[3]), "r"(b[0]), "r"(b[1]));
}
static __device__ __forceinline__ void red4(float* p, float a, float b, float c, float d) {
    asm volatile("red.global.add.v4.f32 [%0], {%1, %2, %3, %4};"
                 :: "l"(p), "f"(a), "f"(b), "f"(c), "f"(d) : "memory");
}
static __device__ __forceinline__ uint32_t f2h2(float a, float b) {
    __half2 h = __floats2half2_rn(a, b);
    return *(uint32_t*)&h;
}
static __device__ __forceinline__ void cvt8h(const float* x, uint4& o) {
    o = make_uint4(f2h2(x[0], x[1]), f2h2(x[2], x[3]),
                   f2h2(x[4], x[5]), f2h2(x[6], x[7]));
}

// ---------------- mask dtype ----------------
static __device__ __forceinline__ bool get_mask(const void* m, int e, int mode) {
    if (mode == 0) return ((const int*)m)[e] != 0;
    if (mode == 1) return ((const unsigned char*)m)[e] != 0;
    return ((const float*)m)[e] != 0.0f;
}
__global__ void probe_mask_kernel(const unsigned char* __restrict__ m) {
    __shared__ int flag[4];
    int t = threadIdx.x;
    if (t < 4) flag[t] = 0;
    __syncthreads();
    int any = 0;
    for (int i = t; i < 4096; i += 256) any |= (int)m[i];
    if (any) atomicOr(&flag[t & 3], 1);
    __syncthreads();
    if (t == 0) {
        int mode;
        if (flag[1] || (flag[0] && (flag[2] | flag[3]))) mode = 1;   // u8/bool
        else if (flag[2] | flag[3])                      mode = 2;   // f32
        else                                             mode = 0;   // i32
        g_mask_mode = mode;
    }
}

__global__ void zero_h_kernel() {
    float4* p = (float4*)g_h;
    const int n = NN * 64 / 4;
    for (int i = blockIdx.x * blockDim.x + threadIdx.x; i < n; i += gridDim.x * blockDim.x)
        p[i] = make_float4(0.f, 0.f, 0.f, 0.f);
}

// ---------------- scatter: z = (attr @ W_in^T)*dinv ; phase*z -> g_h ----------------
// smem: W[64][136]h, A[128][136]h, coef f4[128], u[128], v[128]
#define SC_W  0
#define SC_A  17408
#define SC_CF 52224
#define SC_U  54272
#define SC_V  54784
#define SC_SMEM 55296

__global__ __launch_bounds__(256, 4)
void scatter_kernel(const int* __restrict__ ei, const void* __restrict__ mask,
                    const float* __restrict__ attr, const float* __restrict__ W_in) {
    extern __shared__ char sm[];
    const uint32_t sb = s2u(sm);
    const int t = threadIdx.x, w = t >> 5, lane = t & 31;
    const int mode = g_mask_mode;

    // stage W_in [64 x 128] once (fp16, padded rows of 136 halves)
    for (int g = t; g < 1024; g += 256) {
        int row = g >> 4, k0 = (g & 15) * 8;
        float x[8];
        *(float4*)&x[0] = *(const float4*)(W_in + row * 128 + k0);
        *(float4*)&x[4] = *(const float4*)(W_in + row * 128 + k0 + 4);
        uint4 hv; cvt8h(x, hv);
        *(uint4*)(sm + SC_W + (row * 136 + k0) * 2) = hv;
    }
    __syncthreads();

    // resident B fragments: warp w owns hid cols [8w, 8w+8)
    uint32_t bh[8][2];
    {
        uint32_t ro = (uint32_t)(8 * w + (lane & 7)) * 272;
        #pragma unroll
        for (int ks = 0; ks < 8; ks++) {
            uint32_t co = (uint32_t)(ks * 16 + (lane & 8)) * 2;
            ldsm2(sb + SC_W + ro + co, bh[ks]);
        }
    }
    float4* coef_s = (float4*)(sm + SC_CF);
    int*    u_s    = (int*)(sm + SC_U);
    int*    v_s    = (int*)(sm + SC_V);

    const int n0 = 8 * w, g4 = lane >> 2, t4 = lane & 3, col = n0 + 2 * t4;

    for (int tile = blockIdx.x; tile < NTILES; tile += gridDim.x) {
        __syncthreads();
        const int eb = tile * 128;
        if (t < 128) {
            int e = eb + t;
            int u = ei[e], v = ei[NE + e];
            bool und = get_mask(mask, e, mode);
            float chr, chi, ctr, cti, dinv;
            if (und) { chr = 1.f;  chi = 0.f;   ctr = -1.f;  cti = 0.f;
                       dinv = (u == v) ? 0.f : RSQ2; }
            else     { chr = RSQ2; chi = -RSQ2; ctr = -RSQ2; cti = -RSQ2; dinv = RSQ2; }
            u_s[t] = u; v_s[t] = v;
            coef_s[t] = make_float4(dinv * chr, dinv * chi, dinv * ctr, dinv * cti);
        }
        for (int g = t; g < 2048; g += 256) {           // A tile (fp16)
            int row = g >> 4, k0 = (g & 15) * 8;
            float x[8];
            const float* ap = attr + (size_t)(eb + row) * 128 + k0;
            *(float4*)&x[0] = *(const float4*)ap;
            *(float4*)&x[4] = *(const float4*)(ap + 4);
            uint4 av; cvt8h(x, av);
            *(uint4*)(sm + SC_A + (row * 136 + k0) * 2) = av;
        }
        __syncthreads();

        #pragma unroll 1
        for (int mt = 0; mt < 8; mt++) {
            const int m0 = mt * 16;
            float c[4] = {0.f, 0.f, 0.f, 0.f};
            uint32_t arow  = (uint32_t)(m0 + (lane & 15)) * 272;
            uint32_t acol0 = (uint32_t)((lane >> 4) << 4);
            #pragma unroll
            for (int ks = 0; ks < 8; ks++) {
                uint32_t a4[4];
                ldsm4(sb + SC_A + arow + ks * 32 + acol0, a4);
                mma16816(c, a4, bh[ks]);
            }
            #pragma unroll
            for (int rr = 0; rr < 2; rr++) {
                int el = m0 + g4 + rr * 8;
                float re = rr ? c[2] : c[0], im = rr ? c[3] : c[1];
                float4 cf = coef_s[el];
                int u = u_s[el], v = v_s[el];
                float hvx = cf.x * re - cf.y * im, hvy = cf.x * im + cf.y * re;
                float hux = cf.z * re - cf.w * im, huy = cf.z * im + cf.w * re;
                float pvx = __shfl_xor_sync(0xffffffffu, hvx, 1);
                float pvy = __shfl_xor_sync(0xffffffffu, hvy, 1);
                float pux = __shfl_xor_sync(0xffffffffu, hux, 1);
                float puy = __shfl_xor_sync(0xffffffffu, huy, 1);
                if (t4 & 1) red4(&g_h[(size_t)u * 64 + col - 2], pux, puy, hux, huy);
                else        red4(&g_h[(size_t)v * 64 + col],     hvx, hvy, pvx, pvy);
            }
        }
    }
}

// ---------------- gather: y = dinv*(conj-phase . relu(h)) ; out = [y|attr]@Wcat^T + b ----------------
// smem: W[128][200]h, A0[128][200]h, A1[128][200]h, bias[128]f
#define GA_W  0
#define GA_A0 51200
#define GA_A1 102400
#define GA_BI 153600
#define GA_SMEM 154112

__global__ __launch_bounds__(512, 1)
void gather_kernel(const int* __restrict__ ei, const void* __restrict__ mask,
                   const float* __restrict__ attr,
                   const float* __restrict__ W_out, const float* __restrict__ W_skip,
                   const float* __restrict__ b_skip, const float* __restrict__ bias,
                   float* __restrict__ out) {
    extern __shared__ char sm[];
    const uint32_t sb = s2u(sm);
    const int t = threadIdx.x, w = t >> 5, lane = t & 31;
    const int mode = g_mask_mode;

    // stage Wcat [128 x 192] once: k<64 -> W_out, else W_skip (fp16)
    for (int g = t; g < 3072; g += 512) {
        int row = g / 24, k0 = (g % 24) * 8;
        float x[8];
        if (k0 < 64) {
            *(float4*)&x[0] = *(const float4*)(W_out + row * 64 + k0);
            *(float4*)&x[4] = *(const float4*)(W_out + row * 64 + k0 + 4);
        } else {
            *(float4*)&x[0] = *(const float4*)(W_skip + row * 128 + (k0 - 64));
            *(float4*)&x[4] = *(const float4*)(W_skip + row * 128 + (k0 - 64) + 4);
        }
        uint4 hv; cvt8h(x, hv);
        *(uint4*)(sm + GA_W + (row * 200 + k0) * 2) = hv;
    }
    if (t < 128) ((float*)(sm + GA_BI))[t] = b_skip[t] + bias[t];
    __syncthreads();

    // resident B fragments: warp w (16 warps) owns out cols [8w, 8w+8)
    uint32_t bh[12][2];
    {
        uint32_t ro = (uint32_t)(8 * w + (lane & 7)) * 400;
        #pragma unroll
        for (int ks = 0; ks < 12; ks++) {
            uint32_t co = (uint32_t)(ks * 16 + (lane & 8)) * 2;
            ldsm2(sb + GA_W + ro + co, bh[ks]);
        }
    }
    const int g4 = lane >> 2, t4 = lane & 3;
    float2 b2 = *(float2*)(sm + GA_BI + (8 * w + 2 * t4) * 4);

    const uint32_t abuf[2] = { sb + GA_A0, sb + GA_A1 };

    // ---- staging of one tile into buffer (no internal sync needed) ----
    auto stage = [&](int tile, int bi) {
        const int eb = tile * 128;
        char* buf = sm + (bi ? GA_A1 : GA_A0);
        for (int g = t; g < 2048; g += 512) {           // attr -> k rows [64,192)
            int row = g >> 4, k0 = (g & 15) * 8;
            float x[8];
            const float* ap = attr + (size_t)(eb + row) * 128 + k0;
            *(float4*)&x[0] = *(const float4*)ap;
            *(float4*)&x[4] = *(const float4*)(ap + 4);
            uint4 av; cvt8h(x, av);
            *(uint4*)(buf + (row * 200 + 64 + k0) * 2) = av;
        }
        for (int g = t; g < 4096; g += 512) {           // y -> k rows [0,64)
            int e = g >> 5, p = g & 31;                  // e warp-uniform
            int eg = eb + e;
            int u = ei[eg], v = ei[NE + eg];             // broadcast loads
            bool und = get_mask(mask, eg, mode);
            float ar, ai, br, bi2, dinv = RSQ2;
            if (und) { ar = 1.f;  ai = 0.f;  br = -1.f;  bi2 = 0.f;
                       if (u == v) dinv = 0.f; }
            else     { ar = RSQ2; ai = RSQ2; br = -RSQ2; bi2 = RSQ2; }
            ar *= dinv; ai *= dinv; br *= dinv; bi2 *= dinv;
            float2 hv = *(const float2*)&g_h[(size_t)v * 64 + 2 * p];
            float2 hu = *(const float2*)&g_h[(size_t)u * 64 + 2 * p];
            hv.x = fmaxf(hv.x, 0.f); hv.y = fmaxf(hv.y, 0.f);  // fused ReLU
            hu.x = fmaxf(hu.x, 0.f); hu.y = fmaxf(hu.y, 0.f);
            float yr = ar * hv.x - ai * hv.y + br * hu.x - bi2 * hu.y;
            float yi = ar * hv.y + ai * hv.x + br * hu.y + bi2 * hu.x;
            *(uint32_t*)(buf + e * 400 + 4 * p) = f2h2(yr, yi);
        }
    };

    int tile = blockIdx.x;
    if (tile < NTILES) stage(tile, 0);
    __syncthreads();
    int ph = 0;
    for (; tile < NTILES; tile += gridDim.x) {
        int next = tile + gridDim.x;
        if (next < NTILES) stage(next, ph ^ 1);          // overlap with MMA below

        const int eb = tile * 128;
        #pragma unroll 1
        for (int mt = 0; mt < 8; mt++) {
            const int m0 = mt * 16;
            float c[4] = {0.f, 0.f, 0.f, 0.f};
            uint32_t arow  = (uint32_t)(m0 + (lane & 15)) * 400;
            uint32_t acol0 = (uint32_t)((lane >> 4) << 4);
            #pragma unroll
            for (int ks = 0; ks < 12; ks++) {
                uint32_t a4[4];
                ldsm4(abuf[ph] + arow + ks * 32 + acol0, a4);
                mma16816(c, a4, bh[ks]);
            }
            int e0 = eb + m0 + g4;
            int ca = 8 * w + 2 * t4;
            *(float2*)&out[(size_t)e0 * 128 + ca] =
                make_float2(c[0] + b2.x, c[1] + b2.y);
            *(float2*)&out[(size_t)(e0 + 8) * 128 + ca] =
                make_float2(c[2] + b2.x, c[3] + b2.y);
        }
        __syncthreads();
        ph ^= 1;
    }
}

extern "C" void kernel_launch(void* const* d_in, const int* in_sizes, int n_in,
                              void* d_out, int out_size) {
    const int*   edge_index = (const int*)  d_in[0];
    const void*  mask       =               d_in[1];
    const float* edge_attr  = (const float*)d_in[2];
    const float* W_in       = (const float*)d_in[3];
    const float* W_out      = (const float*)d_in[4];
    const float* W_skip     = (const float*)d_in[5];
    const float* b_skip     = (const float*)d_in[6];
    const float* bias       = (const float*)d_in[7];
    float*       out        = (float*)d_out;

    cudaFuncSetAttribute(scatter_kernel, cudaFuncAttributeMaxDynamicSharedMemorySize, SC_SMEM);
    cudaFuncSetAttribute(gather_kernel,  cudaFuncAttributeMaxDynamicSharedMemorySize, GA_SMEM);

    probe_mask_kernel<<<1, 256>>>((const unsigned char*)mask);
    zero_h_kernel<<<148, 256>>>();
    scatter_kernel<<<592, 256, SC_SMEM>>>(edge_index, mask, edge_attr, W_in);
    gather_kernel<<<148, 512, GA_SMEM>>>(edge_index, mask, edge_attr,
                                         W_out, W_skip, b_skip, bias, out);
}

// round 11
// speedup vs baseline: 3.1252x; 1.1775x over previous
#include <cuda_runtime.h>
#include <cuda_fp16.h>
#include <cstdint>

#define NE 800000
#define NN 50000
#define NTILES (NE/128)
#define RSQ2 0.70710678118654752440f

__device__ float g_h[NN * 64];
__device__ int   g_mask_mode;

// ---------------- helpers ----------------
static __device__ __forceinline__ uint32_t s2u(const void* p) {
    uint32_t a;
    asm("{ .reg .u64 t; cvta.to.shared.u64 t, %1; cvt.u32.u64 %0, t; }" : "=r"(a) : "l"(p));
    return a;
}
static __device__ __forceinline__ void ldsm4(uint32_t a, uint32_t r[4]) {
    asm volatile("ldmatrix.sync.aligned.m8n8.x4.shared.b16 {%0,%1,%2,%3}, [%4];"
                 : "=r"(r[0]), "=r"(r[1]), "=r"(r[2]), "=r"(r[3]) : "r"(a));
}
static __device__ __forceinline__ void ldsm2(uint32_t a, uint32_t r[2]) {
    asm volatile("ldmatrix.sync.aligned.m8n8.x2.shared.b16 {%0,%1}, [%2];"
                 : "=r"(r[0]), "=r"(r[1]) : "r"(a));
}
static __device__ __forceinline__ void mma16816(float c[4], const uint32_t a[4],
                                                const uint32_t b[2]) {
    asm volatile("mma.sync.aligned.m16n8k16.row.col.f32.f16.f16.f32 "
                 "{%0,%1,%2,%3}, {%4,%5,%6,%7}, {%8,%9}, {%0,%1,%2,%3};"
                 : "+f"(c[0]), "+f"(c[1]), "+f"(c[2]), "+f"(c[3])
                 : "r"(a[0]), "r"(a[1]), "r"(a[2]), "r"(a[3]), "r"(b[0]), "r"(b[1]));
}
static __device__ __forceinline__ void red4(float* p, float a, float b, float c, float d) {
    asm volatile("red.global.add.v4.f32 [%0], {%1, %2, %3, %4};"
                 :: "l"(p), "f"(a), "f"(b), "f"(c), "f"(d) : "memory");
}
static __device__ __forceinline__ uint32_t f2h2(float a, float b) {
    __half2 h = __floats2half2_rn(a, b);
    return *(uint32_t*)&h;
}
static __device__ __forceinline__ void cvt8h(const float* x, uint4& o) {
    o = make_uint4(f2h2(x[0], x[1]), f2h2(x[2], x[3]),
                   f2h2(x[4], x[5]), f2h2(x[6], x[7]));
}

// ---------------- mask dtype ----------------
static __device__ __forceinline__ bool get_mask(const void* m, int e, int mode) {
    if (mode == 0) return ((const int*)m)[e] != 0;
    if (mode == 1) return ((const unsigned char*)m)[e] != 0;
    return ((const float*)m)[e] != 0.0f;
}
__global__ void probe_mask_kernel(const unsigned char* __restrict__ m) {
    __shared__ int flag[4];
    int t = threadIdx.x;
    if (t < 4) flag[t] = 0;
    __syncthreads();
    int any = 0;
    for (int i = t; i < 4096; i += 256) any |= (int)m[i];
    if (any) atomicOr(&flag[t & 3], 1);
    __syncthreads();
    if (t == 0) {
        int mode;
        if (flag[1] || (flag[0] && (flag[2] | flag[3]))) mode = 1;   // u8/bool
        else if (flag[2] | flag[3])                      mode = 2;   // f32
        else                                             mode = 0;   // i32
        g_mask_mode = mode;
    }
}

__global__ void zero_h_kernel() {
    float4* p = (float4*)g_h;
    const int n = NN * 64 / 4;
    for (int i = blockIdx.x * blockDim.x + threadIdx.x; i < n; i += gridDim.x * blockDim.x)
        p[i] = make_float4(0.f, 0.f, 0.f, 0.f);
}

// ---------------- scatter: z = (attr @ W_in^T)*dinv ; phase*z -> g_h ----------------
// smem: W[64][136]h, A[128][136]h, coef f4[128], u[128], v[128]
#define SC_W  0
#define SC_A  17408
#define SC_CF 52224
#define SC_U  54272
#define SC_V  54784
#define SC_SMEM 55296

__global__ __launch_bounds__(256, 4)
void scatter_kernel(const int* __restrict__ ei, const void* __restrict__ mask,
                    const float* __restrict__ attr, const float* __restrict__ W_in) {
    extern __shared__ char sm[];
    const uint32_t sb = s2u(sm);
    const int t = threadIdx.x, w = t >> 5, lane = t & 31;
    const int mode = g_mask_mode;

    // stage W_in [64 x 128] once (fp16, padded rows of 136 halves)
    for (int g = t; g < 1024; g += 256) {
        int row = g >> 4, k0 = (g & 15) * 8;
        float x[8];
        *(float4*)&x[0] = *(const float4*)(W_in + row * 128 + k0);
        *(float4*)&x[4] = *(const float4*)(W_in + row * 128 + k0 + 4);
        uint4 hv; cvt8h(x, hv);
        *(uint4*)(sm + SC_W + (row * 136 + k0) * 2) = hv;
    }
    __syncthreads();

    // resident B fragments: warp w owns hid cols [8w, 8w+8)
    uint32_t bh[8][2];
    {
        uint32_t ro = (uint32_t)(8 * w + (lane & 7)) * 272;
        #pragma unroll
        for (int ks = 0; ks < 8; ks++) {
            uint32_t co = (uint32_t)(ks * 16 + (lane & 8)) * 2;
            ldsm2(sb + SC_W + ro + co, bh[ks]);
        }
    }
    float4* coef_s = (float4*)(sm + SC_CF);
    int*    u_s    = (int*)(sm + SC_U);
    int*    v_s    = (int*)(sm + SC_V);

    const int n0 = 8 * w, g4 = lane >> 2, t4 = lane & 3, col = n0 + 2 * t4;

    for (int tile = blockIdx.x; tile < NTILES; tile += gridDim.x) {
        __syncthreads();
        const int eb = tile * 128;
        if (t < 128) {
            int e = eb + t;
            int u = ei[e], v = ei[NE + e];
            bool und = get_mask(mask, e, mode);
            float chr, chi, ctr, cti, dinv;
            if (und) { chr = 1.f;  chi = 0.f;   ctr = -1.f;  cti = 0.f;
                       dinv = (u == v) ? 0.f : RSQ2; }
            else     { chr = RSQ2; chi = -RSQ2; ctr = -RSQ2; cti = -RSQ2; dinv = RSQ2; }
            u_s[t] = u; v_s[t] = v;
            coef_s[t] = make_float4(dinv * chr, dinv * chi, dinv * ctr, dinv * cti);
        }
        for (int g = t; g < 2048; g += 256) {           // A tile (fp16)
            int row = g >> 4, k0 = (g & 15) * 8;
            float x[8];
            const float* ap = attr + (size_t)(eb + row) * 128 + k0;
            *(float4*)&x[0] = *(const float4*)ap;
            *(float4*)&x[4] = *(const float4*)(ap + 4);
            uint4 av; cvt8h(x, av);
            *(uint4*)(sm + SC_A + (row * 136 + k0) * 2) = av;
        }
        __syncthreads();

        #pragma unroll 1
        for (int mt = 0; mt < 8; mt++) {
            const int m0 = mt * 16;
            float c[4] = {0.f, 0.f, 0.f, 0.f};
            uint32_t arow  = (uint32_t)(m0 + (lane & 15)) * 272;
            uint32_t acol0 = (uint32_t)((lane >> 4) << 4);
            #pragma unroll
            for (int ks = 0; ks < 8; ks++) {
                uint32_t a4[4];
                ldsm4(sb + SC_A + arow + ks * 32 + acol0, a4);
                mma16816(c, a4, bh[ks]);
            }
            #pragma unroll
            for (int rr = 0; rr < 2; rr++) {
                int el = m0 + g4 + rr * 8;
                float re = rr ? c[2] : c[0], im = rr ? c[3] : c[1];
                float4 cf = coef_s[el];
                int u = u_s[el], v = v_s[el];
                float hvx = cf.x * re - cf.y * im, hvy = cf.x * im + cf.y * re;
                float hux = cf.z * re - cf.w * im, huy = cf.z * im + cf.w * re;
                float pvx = __shfl_xor_sync(0xffffffffu, hvx, 1);
                float pvy = __shfl_xor_sync(0xffffffffu, hvy, 1);
                float pux = __shfl_xor_sync(0xffffffffu, hux, 1);
                float puy = __shfl_xor_sync(0xffffffffu, huy, 1);
                if (t4 & 1) red4(&g_h[(size_t)u * 64 + col - 2], pux, puy, hux, huy);
                else        red4(&g_h[(size_t)v * 64 + col],     hvx, hvy, pvx, pvy);
            }
        }
    }
}

// ---------------- gather: y = dinv*(conj-phase . relu(h)) ; out = [y|attr]@Wcat^T + b ----------------
// smem: W[128][200]h (reused as A1 after B-frag load), A0[128][200]h, bias[128]f
// 256 threads, 2 CTAs/SM; warp w owns out cols [16w, 16w+16) (2 B strips in regs)
#define GA_W  0
#define GA_A0 51200
#define GA_BI 102400
#define GA_SMEM 102912

__global__ __launch_bounds__(256, 2)
void gather_kernel(const int* __restrict__ ei, const void* __restrict__ mask,
                   const float* __restrict__ attr,
                   const float* __restrict__ W_out, const float* __restrict__ W_skip,
                   const float* __restrict__ b_skip, const float* __restrict__ bias,
                   float* __restrict__ out) {
    extern __shared__ char sm[];
    const uint32_t sb = s2u(sm);
    const int t = threadIdx.x, w = t >> 5, lane = t & 31;
    const int mode = g_mask_mode;

    // stage Wcat [128 x 192] once: k<64 -> W_out, else W_skip (fp16)
    for (int g = t; g < 3072; g += 256) {
        int row = g / 24, k0 = (g % 24) * 8;
        float x[8];
        if (k0 < 64) {
            *(float4*)&x[0] = *(const float4*)(W_out + row * 64 + k0);
            *(float4*)&x[4] = *(const float4*)(W_out + row * 64 + k0 + 4);
        } else {
            *(float4*)&x[0] = *(const float4*)(W_skip + row * 128 + (k0 - 64));
            *(float4*)&x[4] = *(const float4*)(W_skip + row * 128 + (k0 - 64) + 4);
        }
        uint4 hv; cvt8h(x, hv);
        *(uint4*)(sm + GA_W + (row * 200 + k0) * 2) = hv;
    }
    if (t < 128) ((float*)(sm + GA_BI))[t] = b_skip[t] + bias[t];
    __syncthreads();

    // resident B fragments: warp w owns out cols [16w, 16w+16) -> 2 strips
    uint32_t bh[2][12][2];
    #pragma unroll
    for (int s = 0; s < 2; s++) {
        uint32_t ro = (uint32_t)(16 * w + 8 * s + (lane & 7)) * 400;
        #pragma unroll
        for (int ks = 0; ks < 12; ks++) {
            uint32_t co = (uint32_t)(ks * 16 + (lane & 8)) * 2;
            ldsm2(sb + GA_W + ro + co, bh[s][ks]);
        }
    }
    const int g4 = lane >> 2, t4 = lane & 3;
    float2 b2[2];
    b2[0] = *(float2*)(sm + GA_BI + (16 * w + 2 * t4) * 4);
    b2[1] = *(float2*)(sm + GA_BI + (16 * w + 8 + 2 * t4) * 4);
    __syncthreads();   // B frags read -> W region reusable as A1

    const uint32_t abuf[2] = { sb + GA_A0, sb + GA_W };

    // ---- stage one tile into buffer (no internal sync needed) ----
    auto stage = [&](int tile, int bi) {
        const int eb = tile * 128;
        char* buf = sm + (bi ? GA_W : GA_A0);
        for (int g = t; g < 2048; g += 256) {           // attr -> k rows [64,192)
            int row = g >> 4, k0 = (g & 15) * 8;
            float x[8];
            const float* ap = attr + (size_t)(eb + row) * 128 + k0;
            *(float4*)&x[0] = *(const float4*)ap;
            *(float4*)&x[4] = *(const float4*)(ap + 4);
            uint4 av; cvt8h(x, av);
            *(uint4*)(buf + (row * 200 + 64 + k0) * 2) = av;
        }
        for (int g = t; g < 4096; g += 256) {           // y -> k rows [0,64)
            int e = g >> 5, p = g & 31;                  // e warp-uniform
            int eg = eb + e;
            int u = ei[eg], v = ei[NE + eg];             // broadcast loads
            bool und = get_mask(mask, eg, mode);
            float ar, ai, br, bi2, dinv = RSQ2;
            if (und) { ar = 1.f;  ai = 0.f;  br = -1.f;  bi2 = 0.f;
                       if (u == v) dinv = 0.f; }
            else     { ar = RSQ2; ai = RSQ2; br = -RSQ2; bi2 = RSQ2; }
            ar *= dinv; ai *= dinv; br *= dinv; bi2 *= dinv;
            float2 hv = *(const float2*)&g_h[(size_t)v * 64 + 2 * p];
            float2 hu = *(const float2*)&g_h[(size_t)u * 64 + 2 * p];
            hv.x = fmaxf(hv.x, 0.f); hv.y = fmaxf(hv.y, 0.f);  // fused ReLU
            hu.x = fmaxf(hu.x, 0.f); hu.y = fmaxf(hu.y, 0.f);
            float yr = ar * hv.x - ai * hv.y + br * hu.x - bi2 * hu.y;
            float yi = ar * hv.y + ai * hv.x + br * hu.y + bi2 * hu.x;
            *(uint32_t*)(buf + e * 400 + 4 * p) = f2h2(yr, yi);
        }
    };

    int tile = blockIdx.x;
    if (tile < NTILES) stage(tile, 0);
    __syncthreads();
    int ph = 0;
    for (; tile < NTILES; tile += gridDim.x) {
        int next = tile + gridDim.x;
        if (next < NTILES) stage(next, ph ^ 1);          // overlap with MMA below

        const int eb = tile * 128;
        #pragma unroll 1
        for (int mt = 0; mt < 8; mt++) {
            const int m0 = mt * 16;
            float c0[4] = {0.f, 0.f, 0.f, 0.f};
            float c1[4] = {0.f, 0.f, 0.f, 0.f};
            uint32_t arow  = (uint32_t)(m0 + (lane & 15)) * 400;
            uint32_t acol0 = (uint32_t)((lane >> 4) << 4);
            #pragma unroll
            for (int ks = 0; ks < 12; ks++) {
                uint32_t a4[4];
                ldsm4(abuf[ph] + arow + ks * 32 + acol0, a4);
                mma16816(c0, a4, bh[0][ks]);
                mma16816(c1, a4, bh[1][ks]);
            }
            int e0 = eb + m0 + g4;
            int ca = 16 * w + 2 * t4;
            *(float2*)&out[(size_t)e0 * 128 + ca] =
                make_float2(c0[0] + b2[0].x, c0[1] + b2[0].y);
            *(float2*)&out[(size_t)(e0 + 8) * 128 + ca] =
                make_float2(c0[2] + b2[0].x, c0[3] + b2[0].y);
            *(float2*)&out[(size_t)e0 * 128 + ca + 8] =
                make_float2(c1[0] + b2[1].x, c1[1] + b2[1].y);
            *(float2*)&out[(size_t)(e0 + 8) * 128 + ca + 8] =
                make_float2(c1[2] + b2[1].x, c1[3] + b2[1].y);
        }
        __syncthreads();
        ph ^= 1;
    }
}

extern "C" void kernel_launch(void* const* d_in, const int* in_sizes, int n_in,
                              void* d_out, int out_size) {
    const int*   edge_index = (const int*)  d_in[0];
    const void*  mask       =               d_in[1];
    const float* edge_attr  = (const float*)d_in[2];
    const float* W_in       = (const float*)d_in[3];
    const float* W_out      = (const float*)d_in[4];
    const float* W_skip     = (const float*)d_in[5];
    const float* b_skip     = (const float*)d_in[6];
    const float* bias       = (const float*)d_in[7];
    float*       out        = (float*)d_out;

    cudaFuncSetAttribute(scatter_kernel, cudaFuncAttributeMaxDynamicSharedMemorySize, SC_SMEM);
    cudaFuncSetAttribute(gather_kernel,  cudaFuncAttributeMaxDynamicSharedMemorySize, GA_SMEM);

    probe_mask_kernel<<<1, 256>>>((const unsigned char*)mask);
    zero_h_kernel<<<148, 256>>>();
    scatter_kernel<<<592, 256, SC_SMEM>>>(edge_index, mask, edge_attr, W_in);
    gather_kernel<<<296, 256, GA_SMEM>>>(edge_index, mask, edge_attr,
                                         W_out, W_skip, b_skip, bias, out);
}